// round 10
// baseline (speedup 1.0000x reference)
#include <cuda_runtime.h>

#define BATCH 4
#define CCH   512
#define AF    64
#define NPIX  4096   // 64*64

// ---- scratch (static device arrays; no allocation in kernel_launch) ----
__device__ float g_F[BATCH * NPIX * AF];          // ff  [b][n][a]   4 MB
__device__ float g_G[BATCH * NPIX * AF];          // gf  [b][n][a]   4 MB
__device__ float g_H[BATCH * NPIX * CCH];         // hf  [b][m][c]  32 MB
__device__ float g_S[(size_t)BATCH * NPIX * NPIX];// scores/probs  256 MB

// ============================================================================
// Projection GEMM: Out[b][n][j] = sum_k X[b][k][n] * W[k][j] + bias[j]
// X is k-major (stride NPIX), W row-major [512][J]. Both naturally k-major ->
// direct smem copies. 64x64 tile, KT=16, 256 threads, 4x4 microtile.
// TARGET: 0 -> g_F (J=64), 1 -> g_G (J=64), 2 -> g_H (J=512)
// ============================================================================
template<int J, int TARGET>
__global__ __launch_bounds__(256) void proj_kernel(
    const float* __restrict__ X, const float* __restrict__ W,
    const float* __restrict__ bias)
{
    __shared__ float As[16][68];   // As[k][n]
    __shared__ float Bs[16][68];   // Bs[k][j]

    float* Out = (TARGET == 0) ? g_F : (TARGET == 1) ? g_G : g_H;

    const int b  = blockIdx.z;
    const int n0 = blockIdx.x * 64;
    const int j0 = blockIdx.y * 64;
    const float* Xb = X + (size_t)b * CCH * NPIX;

    const int t  = threadIdx.x;
    const int tx = t & 15, ty = t >> 4;
    const int lk = t >> 4;           // 0..15
    const int lc = (t & 15) * 4;     // 0..60

    float acc[4][4] = {};

    for (int k0 = 0; k0 < CCH; k0 += 16) {
        float4 va = *(const float4*)&Xb[(size_t)(k0 + lk) * NPIX + n0 + lc];
        float4 vb = *(const float4*)&W[(k0 + lk) * J + j0 + lc];
        *(float4*)&As[lk][lc] = va;
        *(float4*)&Bs[lk][lc] = vb;
        __syncthreads();
        #pragma unroll
        for (int k = 0; k < 16; k++) {
            float4 a4 = *(const float4*)&As[k][ty * 4];
            float4 b4 = *(const float4*)&Bs[k][tx * 4];
            const float av[4] = {a4.x, a4.y, a4.z, a4.w};
            const float bv[4] = {b4.x, b4.y, b4.z, b4.w};
            #pragma unroll
            for (int i = 0; i < 4; i++)
                #pragma unroll
                for (int j = 0; j < 4; j++)
                    acc[i][j] = fmaf(av[i], bv[j], acc[i][j]);
        }
        __syncthreads();
    }

    #pragma unroll
    for (int i = 0; i < 4; i++) {
        const int n = n0 + ty * 4 + i;
        #pragma unroll
        for (int j = 0; j < 4; j++) {
            const int jj = j0 + tx * 4 + j;
            Out[((size_t)b * NPIX + n) * J + jj] = acc[i][j] + bias[jj];
        }
    }
}

// ============================================================================
// Scores: S[b][n][m] = sum_a G[b][n][a] * F[b][m][a]   (K=64, single K-tile)
// Both operands k-contiguous -> transpose on load into k-major smem.
// ============================================================================
__global__ __launch_bounds__(256) void score_kernel()
{
    __shared__ float Gs[64][65];   // Gs[k][n]
    __shared__ float Fs[64][65];   // Fs[k][m]

    const int b  = blockIdx.z;
    const int n0 = blockIdx.x * 64;
    const int m0 = blockIdx.y * 64;
    const float* Gb = g_G + (size_t)b * NPIX * AF;
    const float* Fb = g_F + (size_t)b * NPIX * AF;

    const int t = threadIdx.x;

    #pragma unroll
    for (int it = 0; it < 4; it++) {
        int idx = t + it * 256;
        int r   = idx >> 4;          // 0..63 row (n or m)
        int c4  = (idx & 15) * 4;    // k quad
        float4 vg = *(const float4*)&Gb[(size_t)(n0 + r) * AF + c4];
        float4 vf = *(const float4*)&Fb[(size_t)(m0 + r) * AF + c4];
        Gs[c4 + 0][r] = vg.x; Gs[c4 + 1][r] = vg.y;
        Gs[c4 + 2][r] = vg.z; Gs[c4 + 3][r] = vg.w;
        Fs[c4 + 0][r] = vf.x; Fs[c4 + 1][r] = vf.y;
        Fs[c4 + 2][r] = vf.z; Fs[c4 + 3][r] = vf.w;
    }
    __syncthreads();

    const int tx = t & 15, ty = t >> 4;
    float acc[4][4] = {};

    #pragma unroll 16
    for (int k = 0; k < 64; k++) {
        float av[4], bv[4];
        #pragma unroll
        for (int i = 0; i < 4; i++) av[i] = Gs[k][ty * 4 + i];
        #pragma unroll
        for (int j = 0; j < 4; j++) bv[j] = Fs[k][tx * 4 + j];
        #pragma unroll
        for (int i = 0; i < 4; i++)
            #pragma unroll
            for (int j = 0; j < 4; j++)
                acc[i][j] = fmaf(av[i], bv[j], acc[i][j]);
    }

    float* Sb = g_S + (size_t)b * NPIX * NPIX;
    #pragma unroll
    for (int i = 0; i < 4; i++)
        #pragma unroll
        for (int j = 0; j < 4; j++)
            Sb[(size_t)(n0 + ty * 4 + i) * NPIX + m0 + tx * 4 + j] = acc[i][j];
}

// ============================================================================
// Softmax over last axis (4096) — one 256-thread CTA per row, 16 elems/thread.
// In-place on g_S.
// ============================================================================
__global__ __launch_bounds__(256) void softmax_kernel()
{
    const size_t row = blockIdx.x;
    float* Srow = g_S + row * (size_t)NPIX;
    const int t = threadIdx.x;

    float v[16];
    float mx = -1e30f;
    #pragma unroll
    for (int i = 0; i < 16; i++) {
        v[i] = Srow[t + i * 256];
        mx = fmaxf(mx, v[i]);
    }

    __shared__ float red[256];
    red[t] = mx;
    __syncthreads();
    #pragma unroll
    for (int s = 128; s > 0; s >>= 1) {
        if (t < s) red[t] = fmaxf(red[t], red[t + s]);
        __syncthreads();
    }
    mx = red[0];
    __syncthreads();

    float sum = 0.f;
    #pragma unroll
    for (int i = 0; i < 16; i++) {
        v[i] = __expf(v[i] - mx);
        sum += v[i];
    }
    red[t] = sum;
    __syncthreads();
    #pragma unroll
    for (int s = 128; s > 0; s >>= 1) {
        if (t < s) red[t] += red[t + s];
        __syncthreads();
    }
    const float inv = 1.f / red[0];

    #pragma unroll
    for (int i = 0; i < 16; i++)
        Srow[t + i * 256] = v[i] * inv;
}

// ============================================================================
// Output GEMM + epilogue:
//   o[b][n][c] = sum_m P[b][n][m] * H[b][m][c]
//   y_flat[idx] = scale * o_flat[idx] + x_flat[idx]  (raw reshape -> same flat)
// A operand (P) is k-contiguous -> transpose on load. B operand (H) k-major.
// ============================================================================
__global__ __launch_bounds__(256) void out_kernel(
    const float* __restrict__ X, const float* __restrict__ scale,
    float* __restrict__ Y)
{
    __shared__ float As[16][68];   // As[k][n] = P[n0+n][k0+k]
    __shared__ float Bs[16][68];   // Bs[k][c] = H[k0+k][c0+c]

    const int b  = blockIdx.z;
    const int n0 = blockIdx.x * 64;
    const int c0 = blockIdx.y * 64;
    const float* Pb = g_S + (size_t)b * NPIX * NPIX;
    const float* Hb = g_H + (size_t)b * NPIX * CCH;

    const int t  = threadIdx.x;
    const int tx = t & 15, ty = t >> 4;
    const int ar = t >> 2;           // 0..63 : n for A transpose load
    const int aq = (t & 3) * 4;      // k quad
    const int bk = t >> 4;           // 0..15 : k for B load
    const int bc = (t & 15) * 4;     // c quad

    const float sc = __ldg(scale);
    float acc[4][4] = {};

    for (int k0 = 0; k0 < NPIX; k0 += 16) {
        float4 va = *(const float4*)&Pb[(size_t)(n0 + ar) * NPIX + k0 + aq];
        float4 vb = *(const float4*)&Hb[(size_t)(k0 + bk) * CCH + c0 + bc];
        As[aq + 0][ar] = va.x; As[aq + 1][ar] = va.y;
        As[aq + 2][ar] = va.z; As[aq + 3][ar] = va.w;
        *(float4*)&Bs[bk][bc] = vb;
        __syncthreads();
        #pragma unroll
        for (int k = 0; k < 16; k++) {
            float4 a4 = *(const float4*)&As[k][ty * 4];
            float4 b4 = *(const float4*)&Bs[k][tx * 4];
            const float av[4] = {a4.x, a4.y, a4.z, a4.w};
            const float bv[4] = {b4.x, b4.y, b4.z, b4.w};
            #pragma unroll
            for (int i = 0; i < 4; i++)
                #pragma unroll
                for (int j = 0; j < 4; j++)
                    acc[i][j] = fmaf(av[i], bv[j], acc[i][j]);
        }
        __syncthreads();
    }

    #pragma unroll
    for (int i = 0; i < 4; i++) {
        #pragma unroll
        for (int j = 0; j < 4; j++) {
            size_t idx = ((size_t)b * NPIX + n0 + ty * 4 + i) * CCH + c0 + tx * 4 + j;
            Y[idx] = sc * acc[i][j] + X[idx];
        }
    }
}

// ============================================================================
extern "C" void kernel_launch(void* const* d_in, const int* in_sizes, int n_in,
                              void* d_out, int out_size)
{
    const float* x     = (const float*)d_in[0];
    const float* Wf    = (const float*)d_in[1];
    const float* bf    = (const float*)d_in[2];
    const float* Wg    = (const float*)d_in[3];
    const float* bg    = (const float*)d_in[4];
    const float* Wh    = (const float*)d_in[5];
    const float* bh    = (const float*)d_in[6];
    const float* scale = (const float*)d_in[7];
    float* y = (float*)d_out;

    dim3 blk(256);

    // projections
    proj_kernel<64, 0><<<dim3(NPIX / 64, 1, BATCH), blk>>>(x, Wf, bf);
    proj_kernel<64, 1><<<dim3(NPIX / 64, 1, BATCH), blk>>>(x, Wg, bg);
    proj_kernel<512, 2><<<dim3(NPIX / 64, CCH / 64, BATCH), blk>>>(x, Wh, bh);

    // scores
    score_kernel<<<dim3(NPIX / 64, NPIX / 64, BATCH), blk>>>();

    // softmax (one CTA per row)
    softmax_kernel<<<BATCH * NPIX, blk>>>();

    // o = P @ H, fused epilogue
    out_kernel<<<dim3(NPIX / 64, CCH / 64, BATCH), blk>>>(x, scale, y);
}

// round 11
// speedup vs baseline: 1.0006x; 1.0006x over previous
#include <cuda_runtime.h>

#define BATCH 4
#define CCH   512
#define AF    64
#define NPIX  4096   // 64*64

// ---- scratch (static device arrays; no allocation in kernel_launch) ----
__device__ float g_F[BATCH * NPIX * AF];          // ff  [b][n][a]   4 MB
__device__ float g_G[BATCH * NPIX * AF];          // gf  [b][n][a]   4 MB
__device__ float g_H[BATCH * NPIX * CCH];         // hf  [b][m][c]  32 MB
__device__ float g_S[(size_t)BATCH * NPIX * NPIX];// scores/probs  256 MB

// ============================================================================
// Projection GEMM: Out[b][n][j] = sum_k X[b][k][n] * W[k][j] + bias[j]
// X is k-major (stride NPIX), W row-major [512][J]. Both naturally k-major ->
// direct smem copies. 64x64 tile, KT=16, 256 threads, 4x4 microtile.
// TARGET: 0 -> g_F (J=64), 1 -> g_G (J=64), 2 -> g_H (J=512)
// ============================================================================
template<int J, int TARGET>
__global__ __launch_bounds__(256) void proj_kernel(
    const float* __restrict__ X, const float* __restrict__ W,
    const float* __restrict__ bias)
{
    __shared__ float As[16][68];   // As[k][n]
    __shared__ float Bs[16][68];   // Bs[k][j]

    float* Out = (TARGET == 0) ? g_F : (TARGET == 1) ? g_G : g_H;

    const int b  = blockIdx.z;
    const int n0 = blockIdx.x * 64;
    const int j0 = blockIdx.y * 64;
    const float* Xb = X + (size_t)b * CCH * NPIX;

    const int t  = threadIdx.x;
    const int tx = t & 15, ty = t >> 4;
    const int lk = t >> 4;           // 0..15
    const int lc = (t & 15) * 4;     // 0..60

    float acc[4][4] = {};

    for (int k0 = 0; k0 < CCH; k0 += 16) {
        float4 va = *(const float4*)&Xb[(size_t)(k0 + lk) * NPIX + n0 + lc];
        float4 vb = *(const float4*)&W[(k0 + lk) * J + j0 + lc];
        *(float4*)&As[lk][lc] = va;
        *(float4*)&Bs[lk][lc] = vb;
        __syncthreads();
        #pragma unroll
        for (int k = 0; k < 16; k++) {
            float4 a4 = *(const float4*)&As[k][ty * 4];
            float4 b4 = *(const float4*)&Bs[k][tx * 4];
            const float av[4] = {a4.x, a4.y, a4.z, a4.w};
            const float bv[4] = {b4.x, b4.y, b4.z, b4.w};
            #pragma unroll
            for (int i = 0; i < 4; i++)
                #pragma unroll
                for (int j = 0; j < 4; j++)
                    acc[i][j] = fmaf(av[i], bv[j], acc[i][j]);
        }
        __syncthreads();
    }

    #pragma unroll
    for (int i = 0; i < 4; i++) {
        const int n = n0 + ty * 4 + i;
        #pragma unroll
        for (int j = 0; j < 4; j++) {
            const int jj = j0 + tx * 4 + j;
            Out[((size_t)b * NPIX + n) * J + jj] = acc[i][j] + bias[jj];
        }
    }
}

// ============================================================================
// Scores: S[b][n][m] = sum_a G[b][n][a] * F[b][m][a]   (K=64, single K-tile)
// Both operands k-contiguous -> transpose on load into k-major smem.
// ============================================================================
__global__ __launch_bounds__(256) void score_kernel()
{
    __shared__ float Gs[64][65];   // Gs[k][n]
    __shared__ float Fs[64][65];   // Fs[k][m]

    const int b  = blockIdx.z;
    const int n0 = blockIdx.x * 64;
    const int m0 = blockIdx.y * 64;
    const float* Gb = g_G + (size_t)b * NPIX * AF;
    const float* Fb = g_F + (size_t)b * NPIX * AF;

    const int t = threadIdx.x;

    #pragma unroll
    for (int it = 0; it < 4; it++) {
        int idx = t + it * 256;
        int r   = idx >> 4;          // 0..63 row (n or m)
        int c4  = (idx & 15) * 4;    // k quad
        float4 vg = *(const float4*)&Gb[(size_t)(n0 + r) * AF + c4];
        float4 vf = *(const float4*)&Fb[(size_t)(m0 + r) * AF + c4];
        Gs[c4 + 0][r] = vg.x; Gs[c4 + 1][r] = vg.y;
        Gs[c4 + 2][r] = vg.z; Gs[c4 + 3][r] = vg.w;
        Fs[c4 + 0][r] = vf.x; Fs[c4 + 1][r] = vf.y;
        Fs[c4 + 2][r] = vf.z; Fs[c4 + 3][r] = vf.w;
    }
    __syncthreads();

    const int tx = t & 15, ty = t >> 4;
    float acc[4][4] = {};

    #pragma unroll 16
    for (int k = 0; k < 64; k++) {
        float av[4], bv[4];
        #pragma unroll
        for (int i = 0; i < 4; i++) av[i] = Gs[k][ty * 4 + i];
        #pragma unroll
        for (int j = 0; j < 4; j++) bv[j] = Fs[k][tx * 4 + j];
        #pragma unroll
        for (int i = 0; i < 4; i++)
            #pragma unroll
            for (int j = 0; j < 4; j++)
                acc[i][j] = fmaf(av[i], bv[j], acc[i][j]);
    }

    float* Sb = g_S + (size_t)b * NPIX * NPIX;
    #pragma unroll
    for (int i = 0; i < 4; i++)
        #pragma unroll
        for (int j = 0; j < 4; j++)
            Sb[(size_t)(n0 + ty * 4 + i) * NPIX + m0 + tx * 4 + j] = acc[i][j];
}

// ============================================================================
// Softmax over last axis (4096) — one 256-thread CTA per row, 16 elems/thread.
// In-place on g_S.
// ============================================================================
__global__ __launch_bounds__(256) void softmax_kernel()
{
    const size_t row = blockIdx.x;
    float* Srow = g_S + row * (size_t)NPIX;
    const int t = threadIdx.x;

    float v[16];
    float mx = -1e30f;
    #pragma unroll
    for (int i = 0; i < 16; i++) {
        v[i] = Srow[t + i * 256];
        mx = fmaxf(mx, v[i]);
    }

    __shared__ float red[256];
    red[t] = mx;
    __syncthreads();
    #pragma unroll
    for (int s = 128; s > 0; s >>= 1) {
        if (t < s) red[t] = fmaxf(red[t], red[t + s]);
        __syncthreads();
    }
    mx = red[0];
    __syncthreads();

    float sum = 0.f;
    #pragma unroll
    for (int i = 0; i < 16; i++) {
        v[i] = __expf(v[i] - mx);
        sum += v[i];
    }
    red[t] = sum;
    __syncthreads();
    #pragma unroll
    for (int s = 128; s > 0; s >>= 1) {
        if (t < s) red[t] += red[t + s];
        __syncthreads();
    }
    const float inv = 1.f / red[0];

    #pragma unroll
    for (int i = 0; i < 16; i++)
        Srow[t + i * 256] = v[i] * inv;
}

// ============================================================================
// Output GEMM + epilogue:
//   o[b][n][c] = sum_m P[b][n][m] * H[b][m][c]
//   y_flat[idx] = scale * o_flat[idx] + x_flat[idx]  (raw reshape -> same flat)
// A operand (P) is k-contiguous -> transpose on load. B operand (H) k-major.
// ============================================================================
__global__ __launch_bounds__(256) void out_kernel(
    const float* __restrict__ X, const float* __restrict__ scale,
    float* __restrict__ Y)
{
    __shared__ float As[16][68];   // As[k][n] = P[n0+n][k0+k]
    __shared__ float Bs[16][68];   // Bs[k][c] = H[k0+k][c0+c]

    const int b  = blockIdx.z;
    const int n0 = blockIdx.x * 64;
    const int c0 = blockIdx.y * 64;
    const float* Pb = g_S + (size_t)b * NPIX * NPIX;
    const float* Hb = g_H + (size_t)b * NPIX * CCH;

    const int t  = threadIdx.x;
    const int tx = t & 15, ty = t >> 4;
    const int ar = t >> 2;           // 0..63 : n for A transpose load
    const int aq = (t & 3) * 4;      // k quad
    const int bk = t >> 4;           // 0..15 : k for B load
    const int bc = (t & 15) * 4;     // c quad

    const float sc = __ldg(scale);
    float acc[4][4] = {};

    for (int k0 = 0; k0 < NPIX; k0 += 16) {
        float4 va = *(const float4*)&Pb[(size_t)(n0 + ar) * NPIX + k0 + aq];
        float4 vb = *(const float4*)&Hb[(size_t)(k0 + bk) * CCH + c0 + bc];
        As[aq + 0][ar] = va.x; As[aq + 1][ar] = va.y;
        As[aq + 2][ar] = va.z; As[aq + 3][ar] = va.w;
        *(float4*)&Bs[bk][bc] = vb;
        __syncthreads();
        #pragma unroll
        for (int k = 0; k < 16; k++) {
            float4 a4 = *(const float4*)&As[k][ty * 4];
            float4 b4 = *(const float4*)&Bs[k][tx * 4];
            const float av[4] = {a4.x, a4.y, a4.z, a4.w};
            const float bv[4] = {b4.x, b4.y, b4.z, b4.w};
            #pragma unroll
            for (int i = 0; i < 4; i++)
                #pragma unroll
                for (int j = 0; j < 4; j++)
                    acc[i][j] = fmaf(av[i], bv[j], acc[i][j]);
        }
        __syncthreads();
    }

    #pragma unroll
    for (int i = 0; i < 4; i++) {
        #pragma unroll
        for (int j = 0; j < 4; j++) {
            size_t idx = ((size_t)b * NPIX + n0 + ty * 4 + i) * CCH + c0 + tx * 4 + j;
            Y[idx] = sc * acc[i][j] + X[idx];
        }
    }
}

// ============================================================================
extern "C" void kernel_launch(void* const* d_in, const int* in_sizes, int n_in,
                              void* d_out, int out_size)
{
    const float* x     = (const float*)d_in[0];
    const float* Wf    = (const float*)d_in[1];
    const float* bf    = (const float*)d_in[2];
    const float* Wg    = (const float*)d_in[3];
    const float* bg    = (const float*)d_in[4];
    const float* Wh    = (const float*)d_in[5];
    const float* bh    = (const float*)d_in[6];
    const float* scale = (const float*)d_in[7];
    float* y = (float*)d_out;

    dim3 blk(256);

    // projections
    proj_kernel<64, 0><<<dim3(NPIX / 64, 1, BATCH), blk>>>(x, Wf, bf);
    proj_kernel<64, 1><<<dim3(NPIX / 64, 1, BATCH), blk>>>(x, Wg, bg);
    proj_kernel<512, 2><<<dim3(NPIX / 64, CCH / 64, BATCH), blk>>>(x, Wh, bh);

    // scores
    score_kernel<<<dim3(NPIX / 64, NPIX / 64, BATCH), blk>>>();

    // softmax (one CTA per row)
    softmax_kernel<<<BATCH * NPIX, blk>>>();

    // o = P @ H, fused epilogue
    out_kernel<<<dim3(NPIX / 64, CCH / 64, BATCH), blk>>>(x, scale, y);
}

// round 12
// speedup vs baseline: 1.0011x; 1.0006x over previous
#include <cuda_runtime.h>

#define BATCH 4
#define CCH   512
#define AF    64
#define NPIX  4096   // 64*64

// ---- scratch (static device arrays; no allocation in kernel_launch) ----
__device__ float g_F[BATCH * NPIX * AF];          // ff  [b][n][a]   4 MB
__device__ float g_G[BATCH * NPIX * AF];          // gf  [b][n][a]   4 MB
__device__ float g_H[BATCH * NPIX * CCH];         // hf  [b][m][c]  32 MB
__device__ float g_S[(size_t)BATCH * NPIX * NPIX];// scores/probs  256 MB

// ============================================================================
// Projection GEMM: Out[b][n][j] = sum_k X[b][k][n] * W[k][j] + bias[j]
// X is k-major (stride NPIX), W row-major [512][J]. Both naturally k-major ->
// direct smem copies. 64x64 tile, KT=16, 256 threads, 4x4 microtile.
// TARGET: 0 -> g_F (J=64), 1 -> g_G (J=64), 2 -> g_H (J=512)
// ============================================================================
template<int J, int TARGET>
__global__ __launch_bounds__(256) void proj_kernel(
    const float* __restrict__ X, const float* __restrict__ W,
    const float* __restrict__ bias)
{
    __shared__ float As[16][68];   // As[k][n]
    __shared__ float Bs[16][68];   // Bs[k][j]

    float* Out = (TARGET == 0) ? g_F : (TARGET == 1) ? g_G : g_H;

    const int b  = blockIdx.z;
    const int n0 = blockIdx.x * 64;
    const int j0 = blockIdx.y * 64;
    const float* Xb = X + (size_t)b * CCH * NPIX;

    const int t  = threadIdx.x;
    const int tx = t & 15, ty = t >> 4;
    const int lk = t >> 4;           // 0..15
    const int lc = (t & 15) * 4;     // 0..60

    float acc[4][4] = {};

    for (int k0 = 0; k0 < CCH; k0 += 16) {
        float4 va = *(const float4*)&Xb[(size_t)(k0 + lk) * NPIX + n0 + lc];
        float4 vb = *(const float4*)&W[(k0 + lk) * J + j0 + lc];
        *(float4*)&As[lk][lc] = va;
        *(float4*)&Bs[lk][lc] = vb;
        __syncthreads();
        #pragma unroll
        for (int k = 0; k < 16; k++) {
            float4 a4 = *(const float4*)&As[k][ty * 4];
            float4 b4 = *(const float4*)&Bs[k][tx * 4];
            const float av[4] = {a4.x, a4.y, a4.z, a4.w};
            const float bv[4] = {b4.x, b4.y, b4.z, b4.w};
            #pragma unroll
            for (int i = 0; i < 4; i++)
                #pragma unroll
                for (int j = 0; j < 4; j++)
                    acc[i][j] = fmaf(av[i], bv[j], acc[i][j]);
        }
        __syncthreads();
    }

    #pragma unroll
    for (int i = 0; i < 4; i++) {
        const int n = n0 + ty * 4 + i;
        #pragma unroll
        for (int j = 0; j < 4; j++) {
            const int jj = j0 + tx * 4 + j;
            Out[((size_t)b * NPIX + n) * J + jj] = acc[i][j] + bias[jj];
        }
    }
}

// ============================================================================
// Scores: S[b][n][m] = sum_a G[b][n][a] * F[b][m][a]   (K=64, single K-tile)
// Both operands k-contiguous -> transpose on load into k-major smem.
// ============================================================================
__global__ __launch_bounds__(256) void score_kernel()
{
    __shared__ float Gs[64][65];   // Gs[k][n]
    __shared__ float Fs[64][65];   // Fs[k][m]

    const int b  = blockIdx.z;
    const int n0 = blockIdx.x * 64;
    const int m0 = blockIdx.y * 64;
    const float* Gb = g_G + (size_t)b * NPIX * AF;
    const float* Fb = g_F + (size_t)b * NPIX * AF;

    const int t = threadIdx.x;

    #pragma unroll
    for (int it = 0; it < 4; it++) {
        int idx = t + it * 256;
        int r   = idx >> 4;          // 0..63 row (n or m)
        int c4  = (idx & 15) * 4;    // k quad
        float4 vg = *(const float4*)&Gb[(size_t)(n0 + r) * AF + c4];
        float4 vf = *(const float4*)&Fb[(size_t)(m0 + r) * AF + c4];
        Gs[c4 + 0][r] = vg.x; Gs[c4 + 1][r] = vg.y;
        Gs[c4 + 2][r] = vg.z; Gs[c4 + 3][r] = vg.w;
        Fs[c4 + 0][r] = vf.x; Fs[c4 + 1][r] = vf.y;
        Fs[c4 + 2][r] = vf.z; Fs[c4 + 3][r] = vf.w;
    }
    __syncthreads();

    const int tx = t & 15, ty = t >> 4;
    float acc[4][4] = {};

    #pragma unroll 16
    for (int k = 0; k < 64; k++) {
        float av[4], bv[4];
        #pragma unroll
        for (int i = 0; i < 4; i++) av[i] = Gs[k][ty * 4 + i];
        #pragma unroll
        for (int j = 0; j < 4; j++) bv[j] = Fs[k][tx * 4 + j];
        #pragma unroll
        for (int i = 0; i < 4; i++)
            #pragma unroll
            for (int j = 0; j < 4; j++)
                acc[i][j] = fmaf(av[i], bv[j], acc[i][j]);
    }

    float* Sb = g_S + (size_t)b * NPIX * NPIX;
    #pragma unroll
    for (int i = 0; i < 4; i++)
        #pragma unroll
        for (int j = 0; j < 4; j++)
            Sb[(size_t)(n0 + ty * 4 + i) * NPIX + m0 + tx * 4 + j] = acc[i][j];
}

// ============================================================================
// Softmax over last axis (4096) — one 256-thread CTA per row, 16 elems/thread.
// In-place on g_S.
// ============================================================================
__global__ __launch_bounds__(256) void softmax_kernel()
{
    const size_t row = blockIdx.x;
    float* Srow = g_S + row * (size_t)NPIX;
    const int t = threadIdx.x;

    float v[16];
    float mx = -1e30f;
    #pragma unroll
    for (int i = 0; i < 16; i++) {
        v[i] = Srow[t + i * 256];
        mx = fmaxf(mx, v[i]);
    }

    __shared__ float red[256];
    red[t] = mx;
    __syncthreads();
    #pragma unroll
    for (int s = 128; s > 0; s >>= 1) {
        if (t < s) red[t] = fmaxf(red[t], red[t + s]);
        __syncthreads();
    }
    mx = red[0];
    __syncthreads();

    float sum = 0.f;
    #pragma unroll
    for (int i = 0; i < 16; i++) {
        v[i] = __expf(v[i] - mx);
        sum += v[i];
    }
    red[t] = sum;
    __syncthreads();
    #pragma unroll
    for (int s = 128; s > 0; s >>= 1) {
        if (t < s) red[t] += red[t + s];
        __syncthreads();
    }
    const float inv = 1.f / red[0];

    #pragma unroll
    for (int i = 0; i < 16; i++)
        Srow[t + i * 256] = v[i] * inv;
}

// ============================================================================
// Output GEMM + epilogue:
//   o[b][n][c] = sum_m P[b][n][m] * H[b][m][c]
//   y_flat[idx] = scale * o_flat[idx] + x_flat[idx]  (raw reshape -> same flat)
// A operand (P) is k-contiguous -> transpose on load. B operand (H) k-major.
// ============================================================================
__global__ __launch_bounds__(256) void out_kernel(
    const float* __restrict__ X, const float* __restrict__ scale,
    float* __restrict__ Y)
{
    __shared__ float As[16][68];   // As[k][n] = P[n0+n][k0+k]
    __shared__ float Bs[16][68];   // Bs[k][c] = H[k0+k][c0+c]

    const int b  = blockIdx.z;
    const int n0 = blockIdx.x * 64;
    const int c0 = blockIdx.y * 64;
    const float* Pb = g_S + (size_t)b * NPIX * NPIX;
    const float* Hb = g_H + (size_t)b * NPIX * CCH;

    const int t  = threadIdx.x;
    const int tx = t & 15, ty = t >> 4;
    const int ar = t >> 2;           // 0..63 : n for A transpose load
    const int aq = (t & 3) * 4;      // k quad
    const int bk = t >> 4;           // 0..15 : k for B load
    const int bc = (t & 15) * 4;     // c quad

    const float sc = __ldg(scale);
    float acc[4][4] = {};

    for (int k0 = 0; k0 < NPIX; k0 += 16) {
        float4 va = *(const float4*)&Pb[(size_t)(n0 + ar) * NPIX + k0 + aq];
        float4 vb = *(const float4*)&Hb[(size_t)(k0 + bk) * CCH + c0 + bc];
        As[aq + 0][ar] = va.x; As[aq + 1][ar] = va.y;
        As[aq + 2][ar] = va.z; As[aq + 3][ar] = va.w;
        *(float4*)&Bs[bk][bc] = vb;
        __syncthreads();
        #pragma unroll
        for (int k = 0; k < 16; k++) {
            float4 a4 = *(const float4*)&As[k][ty * 4];
            float4 b4 = *(const float4*)&Bs[k][tx * 4];
            const float av[4] = {a4.x, a4.y, a4.z, a4.w};
            const float bv[4] = {b4.x, b4.y, b4.z, b4.w};
            #pragma unroll
            for (int i = 0; i < 4; i++)
                #pragma unroll
                for (int j = 0; j < 4; j++)
                    acc[i][j] = fmaf(av[i], bv[j], acc[i][j]);
        }
        __syncthreads();
    }

    #pragma unroll
    for (int i = 0; i < 4; i++) {
        #pragma unroll
        for (int j = 0; j < 4; j++) {
            size_t idx = ((size_t)b * NPIX + n0 + ty * 4 + i) * CCH + c0 + tx * 4 + j;
            Y[idx] = sc * acc[i][j] + X[idx];
        }
    }
}

// ============================================================================
extern "C" void kernel_launch(void* const* d_in, const int* in_sizes, int n_in,
                              void* d_out, int out_size)
{
    const float* x     = (const float*)d_in[0];
    const float* Wf    = (const float*)d_in[1];
    const float* bf    = (const float*)d_in[2];
    const float* Wg    = (const float*)d_in[3];
    const float* bg    = (const float*)d_in[4];
    const float* Wh    = (const float*)d_in[5];
    const float* bh    = (const float*)d_in[6];
    const float* scale = (const float*)d_in[7];
    float* y = (float*)d_out;

    dim3 blk(256);

    // projections
    proj_kernel<64, 0><<<dim3(NPIX / 64, 1, BATCH), blk>>>(x, Wf, bf);
    proj_kernel<64, 1><<<dim3(NPIX / 64, 1, BATCH), blk>>>(x, Wg, bg);
    proj_kernel<512, 2><<<dim3(NPIX / 64, CCH / 64, BATCH), blk>>>(x, Wh, bh);

    // scores
    score_kernel<<<dim3(NPIX / 64, NPIX / 64, BATCH), blk>>>();

    // softmax (one CTA per row)
    softmax_kernel<<<BATCH * NPIX, blk>>>();

    // o = P @ H, fused epilogue
    out_kernel<<<dim3(NPIX / 64, CCH / 64, BATCH), blk>>>(x, scale, y);
}